// round 1
// baseline (speedup 1.0000x reference)
#include <cuda_runtime.h>

// LorentzConv2d: B=32, H=W=64, C_in=64, C_out=64 (+1 time), 3x3 s1 p1.
// feat = [ t_rescaled, x_pad[tap, ch=1..63] ]  (K = 1 + 9*63 = 568)
// y_space = feat @ W^T + bias;  out = [ sqrt(|y|^2+1), y_space ]

#define B_    32
#define H_    64
#define W_    64
#define C_    64
#define OC_   64
#define KFEAT 568          // 1 + 9*63

// Pre-transposed weight: Wt[k][o], k-major (so per-tap chunks are contiguous & coalesced)
__device__ float g_Wt[KFEAT * OC_];

__global__ void transpose_w_kernel(const float* __restrict__ w) {
    int idx = blockIdx.x * blockDim.x + threadIdx.x;
    if (idx < KFEAT * OC_) {
        int k = idx >> 6;     // /64
        int o = idx & 63;
        g_Wt[idx] = w[o * KFEAT + k];
    }
}

// Shared memory layout (floats)
#define SM_XT  (C_ * 3 * 66)   // 12672 : transposed 3 input rows with halo: [c][r][66]
#define SM_BS  (63 * OC_)      //  4032 : per-tap weight tile [c-1][o]
#define SM_OS  (W_ * 65)       //  4160 : staged output row [pix][65]
#define SM_PS  (16 * W_)       //  1024 : partial |y|^2 sums [ty][pix]
#define SM_TR  (W_)            //    64 : t_rescaled per pixel
#define SM_FLOATS (SM_XT + SM_BS + SM_OS + SM_PS + SM_TR)   // 21952 floats = 87808 B

__global__ __launch_bounds__(256, 2)
void lorentz_conv_kernel(const float* __restrict__ x,
                         const float* __restrict__ bias,
                         float* __restrict__ out) {
    extern __shared__ float sm[];
    float* xT = sm;                    // [c*3 + r]*66 + wc
    float* Bs = sm + SM_XT;
    float* Os = Bs + SM_BS;
    float* Ps = Os + SM_OS;
    float* Tr = Ps + SM_PS;

    const int tid = threadIdx.x;
    const int tx  = tid & 15;          // pixel group: pixels tx*4 .. tx*4+3
    const int ty  = tid >> 4;          // output group: outs  ty*4 .. ty*4+3
    const int bh  = blockIdx.x;        // b*H + h
    const int b   = bh >> 6;
    const int h   = bh & 63;

    // ---- Stage 1: load 3 input rows (with zero halo) transposed to channel-major ----
    #pragma unroll
    for (int r = 0; r < 3; ++r) {
        const int hr = h + r - 1;
        const bool vr = ((unsigned)hr < (unsigned)H_);
        const float* xrow = x + ((b * H_ + hr) * W_) * C_;
        for (int idx = tid; idx < 66 * C_; idx += 256) {
            const int c  = idx & 63;       // coalesced over channels
            const int wc = idx >> 6;       // 0..65 (halo col)
            float v = 0.f;
            if (vr && wc >= 1 && wc <= W_) v = xrow[(wc - 1) * C_ + c];
            xT[(c * 3 + r) * 66 + wc] = v; // 2-way store conflict, one-time
        }
    }
    __syncthreads();

    // ---- Stage 2: t_rescaled per pixel from channel 0 ----
    if (tid < W_) {
        float s = 0.f;
        #pragma unroll
        for (int r = 0; r < 3; ++r)
            #pragma unroll
            for (int d = 0; d < 3; ++d) {
                float v = fmaxf(xT[r * 66 + tid + d], 1.0f);  // c == 0 rows
                s += v * v;
            }
        Tr[tid] = sqrtf(s - 8.0f);   // (kk-1)*C_CURV = 8
    }
    __syncthreads();

    // ---- Init accumulators: bias + t_rescaled * W[:,0] ----
    float acc[4][4];
    const float4 w0 = *(const float4*)&g_Wt[ty * 4];      // Wt row k=0
    const float4 bb = *(const float4*)&bias[ty * 4];
    #pragma unroll
    for (int i = 0; i < 4; ++i) {
        const float t = Tr[tx * 4 + i];
        acc[i][0] = bb.x + t * w0.x;
        acc[i][1] = bb.y + t * w0.y;
        acc[i][2] = bb.z + t * w0.z;
        acc[i][3] = bb.w + t * w0.w;
    }

    // ---- Main GEMM: 9 taps x 63 channels ----
    for (int tap = 0; tap < 9; ++tap) {
        __syncthreads();   // protect Bs reuse
        {
            const float* src = g_Wt + (1 + tap * 63) * OC_;   // contiguous chunk of Wt
            for (int idx = tid; idx < 63 * OC_; idx += 256) Bs[idx] = src[idx];
        }
        __syncthreads();

        const int r   = tap / 3;
        const int dwp = tap % 3;
        const float* ap = xT + r * 66 + dwp + tx * 4;
        const float* bp = Bs + ty * 4;

        #pragma unroll 3
        for (int c = 1; c < C_; ++c) {
            const float* a = ap + c * 198;       // (c*3 + r)*66 base, conflict-free reads
            const float a0 = a[0], a1 = a[1], a2 = a[2], a3 = a[3];
            const float4 bv = *(const float4*)(bp + (c - 1) * OC_);
            acc[0][0] += a0 * bv.x; acc[0][1] += a0 * bv.y; acc[0][2] += a0 * bv.z; acc[0][3] += a0 * bv.w;
            acc[1][0] += a1 * bv.x; acc[1][1] += a1 * bv.y; acc[1][2] += a1 * bv.z; acc[1][3] += a1 * bv.w;
            acc[2][0] += a2 * bv.x; acc[2][1] += a2 * bv.y; acc[2][2] += a2 * bv.z; acc[2][3] += a2 * bv.w;
            acc[3][0] += a3 * bv.x; acc[3][1] += a3 * bv.y; acc[3][2] += a3 * bv.z; acc[3][3] += a3 * bv.w;
        }
    }

    // ---- Epilogue: stage y_space, reduce |y|^2 across output groups, y_time ----
    #pragma unroll
    for (int i = 0; i < 4; ++i) {
        const int pix = tx * 4 + i;
        float p = 0.f;
        #pragma unroll
        for (int j = 0; j < 4; ++j) {
            const float v = acc[i][j];
            Os[pix * 65 + 1 + ty * 4 + j] = v;
            p += v * v;
        }
        Ps[ty * W_ + pix] = p;
    }
    __syncthreads();

    if (tid < W_) {
        float s = 0.f;
        #pragma unroll
        for (int t = 0; t < 16; ++t) s += Ps[t * W_ + tid];
        Os[tid * 65] = sqrtf(s + 1.0f);
    }
    __syncthreads();

    // ---- Coalesced float4 writeback of the whole row (64*65 floats) ----
    float4* og = (float4*)(out + (size_t)bh * (W_ * 65));
    const float4* ov = (const float4*)Os;
    for (int idx = tid; idx < (W_ * 65) / 4; idx += 256) og[idx] = ov[idx];
}

extern "C" void kernel_launch(void* const* d_in, const int* in_sizes, int n_in,
                              void* d_out, int out_size) {
    const float* x    = (const float*)d_in[0];
    const float* w    = (const float*)d_in[1];
    const float* bias = (const float*)d_in[2];
    float* out = (float*)d_out;

    cudaFuncSetAttribute(lorentz_conv_kernel,
                         cudaFuncAttributeMaxDynamicSharedMemorySize,
                         SM_FLOATS * (int)sizeof(float));

    transpose_w_kernel<<<(KFEAT * OC_ + 255) / 256, 256>>>(w);
    lorentz_conv_kernel<<<B_ * H_, 256, SM_FLOATS * sizeof(float)>>>(x, bias, out);
}

// round 3
// speedup vs baseline: 4.3478x; 4.3478x over previous
#include <cuda_runtime.h>
#include <cuda_bf16.h>
#include <cstdint>

// LorentzConv2d: B=32,H=W=64,C=64,OC=64(+time), 3x3 s1 p1.
// GEMM via warp mma.sync bf16 hi/lo split (3 MMAs). Legacy sm_80 path
// (tcgen05 unavailable: harness compiles PTX at target sm_103, not sm_103a).

__device__ __nv_bfloat16 g_Bhi[9 * 64 * 64];
__device__ __nv_bfloat16 g_Blo[9 * 64 * 64];

__global__ void prep_b_kernel(const float* __restrict__ w) {
    int i = blockIdx.x * blockDim.x + threadIdx.x;    // [tap][o][c]
    if (i < 9 * 64 * 64) {
        int tap = i >> 12, o = (i >> 6) & 63, c = i & 63;
        float v = (c == 0) ? 0.f : w[o * 568 + tap * 63 + c];  // k = 1+tap*63+(c-1)
        __nv_bfloat16 h = __float2bfloat16(v);
        g_Bhi[i] = h;
        g_Blo[i] = __float2bfloat16(v - __bfloat162float(h));
    }
}

// ---------------- helpers ----------------

#define SWZ(o) ((o) ^ (((o) >> 3) & 0x70))

__device__ __forceinline__ uint32_t s2u(const void* p) {
    uint32_t a;
    asm("{ .reg .u64 t; cvta.to.shared.u64 t, %1; cvt.u32.u64 %0, t; }" : "=r"(a) : "l"(p));
    return a;
}

#define CP16(d, s) \
    asm volatile("cp.async.cg.shared.global [%0], [%1], 16;" :: "r"(d), "l"(s) : "memory")

#define LDSM4(r, addr) \
    asm volatile("ldmatrix.sync.aligned.m8n8.x4.shared.b16 {%0,%1,%2,%3}, [%4];" \
        : "=r"((r)[0]), "=r"((r)[1]), "=r"((r)[2]), "=r"((r)[3]) : "r"(addr))

#define MMA(d, a, b0_, b1_) \
    asm volatile("mma.sync.aligned.m16n8k16.row.col.f32.bf16.bf16.f32 " \
        "{%0,%1,%2,%3}, {%4,%5,%6,%7}, {%8,%9}, {%0,%1,%2,%3};" \
        : "+f"((d)[0]), "+f"((d)[1]), "+f"((d)[2]), "+f"((d)[3]) \
        : "r"((a)[0]), "r"((a)[1]), "r"((a)[2]), "r"((a)[3]), "r"(b0_), "r"(b1_))

__device__ __forceinline__ uint32_t pack_bf2(float a, float b) {
    __nv_bfloat162 h = __floats2bfloat162_rn(a, b);
    return *(uint32_t*)&h;
}

// ---------------- smem layout (bytes) ----------------
// [0..512)      t (128 f)
// [512..768)    bias (64 f)
// [768..1024)   w0 (64 f)
// [1024..34816) A_hi  : 264 pixel-slots (4 rows x 66 cols) x 128B, SW128
// [34816..68608) A_lo
// [68608..84992) B stage0 (hi 8KB, lo 8KB), SW128
// [84992..101376) B stage1
// Os (128x65 f = 33280B) overlays A_hi at 1024.
#define T_OFF    0u
#define BIAS_OFF 512u
#define W0_OFF   768u
#define AHI_OFF  1024u
#define ALO_OFF  34816u
#define BST_OFF(st) (68608u + (uint32_t)(st) * 16384u)
#define SMEM_TOTAL 101376

__global__ __launch_bounds__(256, 2)
void lmma_kernel(const float* __restrict__ x, const float* __restrict__ w,
                 const float* __restrict__ bias, float* __restrict__ out)
{
    extern __shared__ char sm[];
    const uint32_t smb = s2u(sm);
    const int tid  = threadIdx.x;
    const int lane = tid & 31;
    const int wid  = tid >> 5;
    const int wm   = wid & 3;          // m span: 32 rows
    const int wn   = wid >> 2;         // n span: 32 cols
    const int blk  = blockIdx.x;       // 0..1023
    const int b    = blk >> 5;
    const int h0   = (blk & 31) * 2;   // 2 image rows per CTA

    // ---- prefetch B taps 0,1 (cp.async) ----
    #pragma unroll
    for (int tap = 0; tap < 2; ++tap) {
        const uint32_t sb = BST_OFF(tap);
        const char* shi = (const char*)g_Bhi + tap * 8192;
        const char* slo = (const char*)g_Blo + tap * 8192;
        for (int i = tid; i < 512; i += 256) {
            uint32_t off = (uint32_t)i * 16u;
            uint32_t d = SWZ(off);
            CP16(smb + sb + d,         shi + off);
            CP16(smb + sb + 8192u + d, slo + off);
        }
        asm volatile("cp.async.commit_group;" ::: "memory");
    }

    // ---- epilogue params + t ----
    if (tid < 64) {
        ((float*)(sm + BIAS_OFF))[tid] = bias[tid];
        ((float*)(sm + W0_OFF))[tid]   = w[tid * 568];   // W[:,0]
    }
    if (tid < 128) {
        const int ir = tid >> 6, wp = tid & 63;
        float s = 0.f;
        #pragma unroll
        for (int r = 0; r < 3; ++r)
            #pragma unroll
            for (int d = 0; d < 3; ++d) {
                const int hg = h0 + ir + r - 1, wg = wp + d - 1;
                float v = 0.f;
                if ((unsigned)hg < 64u && (unsigned)wg < 64u)
                    v = x[(size_t)(((b * 64 + hg) * 64 + wg)) * 64];   // channel 0
                const float m = fmaxf(v, 1.f);
                s += m * m;
            }
        ((float*)(sm + T_OFF))[tid] = sqrtf(s - 8.f);
    }

    // ---- A load: fp32 -> bf16 hi/lo into swizzled smem ----
    // 264 slots = 4 input rows (h0-1..h0+2) x 66 halo cols; 64 ch each.
    {
        const int c4 = tid & 15;                      // float4 index within pixel
        for (int slot = tid >> 4; slot < 264; slot += 16) {
            const int r = slot / 66, c = slot - r * 66;
            const int hg = h0 - 1 + r, wg = c - 1;
            const uint32_t o = SWZ((uint32_t)slot * 128u + (uint32_t)c4 * 8u);
            float4 v = make_float4(0.f, 0.f, 0.f, 0.f);
            if ((unsigned)hg < 64u && (unsigned)wg < 64u)
                v = *(const float4*)(x + (size_t)(((b * 64 + hg) * 64 + wg)) * 64 + c4 * 4);
            uint2 hi, lo;
            hi.x = pack_bf2(v.x, v.y);
            hi.y = pack_bf2(v.z, v.w);
            __nv_bfloat162 h0v = *(__nv_bfloat162*)&hi.x;
            __nv_bfloat162 h1v = *(__nv_bfloat162*)&hi.y;
            lo.x = pack_bf2(v.x - __bfloat162float(h0v.x), v.y - __bfloat162float(h0v.y));
            lo.y = pack_bf2(v.z - __bfloat162float(h1v.x), v.w - __bfloat162float(h1v.y));
            *(uint2*)(sm + AHI_OFF + o) = hi;
            *(uint2*)(sm + ALO_OFF + o) = lo;
        }
    }
    __syncthreads();

    // ---- per-lane invariants ----
    const uint32_t ahalf = (uint32_t)(lane >> 4);         // A k-chunk half
    const uint32_t bhalf = (uint32_t)((lane >> 3) & 1);   // B k-chunk half
    uint32_t bbase[2], bsx[2];
    #pragma unroll
    for (int p = 0; p < 2; ++p) {
        const int nrow = wn * 32 + p * 16 + ((lane & 16) ? 8 : 0) + (lane & 7);
        bbase[p] = (uint32_t)nrow * 128u;
        bsx[p]   = (uint32_t)(nrow & 7);
    }
    const int mloc[2] = { wm * 32 + (lane & 15), wm * 32 + 16 + (lane & 15) };

    float acc[2][4][4];
    #pragma unroll
    for (int mi = 0; mi < 2; ++mi)
        #pragma unroll
        for (int ni = 0; ni < 4; ++ni)
            #pragma unroll
            for (int j = 0; j < 4; ++j) acc[mi][ni][j] = 0.f;

    // ---- main loop over 9 taps ----
    for (int tap = 0; tap < 9; ++tap) {
        if (tap < 8) asm volatile("cp.async.wait_group 1;" ::: "memory");
        else         asm volatile("cp.async.wait_group 0;" ::: "memory");
        __syncthreads();

        const int r = tap / 3, dw = tap - r * 3;
        const uint32_t sbhi = smb + BST_OFF(tap & 1);
        const uint32_t sblo = sbhi + 8192u;

        uint32_t abase[2], asx[2];
        #pragma unroll
        for (int mi = 0; mi < 2; ++mi) {
            const int ir = mloc[mi] >> 6, wp = mloc[mi] & 63;
            const int P = (ir + r) * 66 + wp + dw;
            abase[mi] = (uint32_t)P * 128u;
            asx[mi]   = (uint32_t)(P & 7);
        }

        #pragma unroll
        for (int k = 0; k < 4; ++k) {
            uint32_t ah[2][4], al[2][4], bh[2][4], bl[2][4];
            #pragma unroll
            for (int mi = 0; mi < 2; ++mi) {
                const uint32_t ao = abase[mi] +
                    ((((uint32_t)(k * 2) + ahalf) ^ asx[mi]) << 4);
                LDSM4(ah[mi], smb + AHI_OFF + ao);
                LDSM4(al[mi], smb + ALO_OFF + ao);
            }
            #pragma unroll
            for (int p = 0; p < 2; ++p) {
                const uint32_t bo = bbase[p] +
                    ((((uint32_t)(k * 2) + bhalf) ^ bsx[p]) << 4);
                LDSM4(bh[p], sbhi + bo);
                LDSM4(bl[p], sblo + bo);
            }
            #pragma unroll
            for (int mi = 0; mi < 2; ++mi)
                #pragma unroll
                for (int p = 0; p < 2; ++p)
                    #pragma unroll
                    for (int q = 0; q < 2; ++q) {
                        const int ni = p * 2 + q;
                        MMA(acc[mi][ni], ah[mi], bh[p][q * 2], bh[p][q * 2 + 1]);
                        MMA(acc[mi][ni], ah[mi], bl[p][q * 2], bl[p][q * 2 + 1]);
                        MMA(acc[mi][ni], al[mi], bh[p][q * 2], bh[p][q * 2 + 1]);
                    }
        }

        __syncthreads();   // stage (tap&1) free for reuse
        const int nt = tap + 2;
        if (nt < 9) {
            const uint32_t sb = BST_OFF(nt & 1);
            const char* shi = (const char*)g_Bhi + nt * 8192;
            const char* slo = (const char*)g_Blo + nt * 8192;
            for (int i = tid; i < 512; i += 256) {
                uint32_t off = (uint32_t)i * 16u;
                uint32_t d = SWZ(off);
                CP16(smb + sb + d,         shi + off);
                CP16(smb + sb + 8192u + d, slo + off);
            }
            asm volatile("cp.async.commit_group;" ::: "memory");
        }
    }

    // ---- epilogue: fuse bias + t*W[:,0], stage y_space, y_time, writeback ----
    const float* ts  = (const float*)(sm + T_OFF);
    const float* bs  = (const float*)(sm + BIAS_OFF);
    const float* w0s = (const float*)(sm + W0_OFF);
    float* Os = (float*)(sm + AHI_OFF);       // overlays A (dead now; synced above)

    #pragma unroll
    for (int mi = 0; mi < 2; ++mi) {
        const int m0 = wm * 32 + mi * 16 + (lane >> 2);
        const float t0 = ts[m0], t8 = ts[m0 + 8];
        #pragma unroll
        for (int ni = 0; ni < 4; ++ni) {
            const int n0 = wn * 32 + ni * 8 + (lane & 3) * 2;
            const float b0v = bs[n0],  b1v = bs[n0 + 1];
            const float w0v = w0s[n0], w1v = w0s[n0 + 1];
            Os[m0 * 65 + 1 + n0]           = acc[mi][ni][0] + b0v + t0 * w0v;
            Os[m0 * 65 + 2 + n0]           = acc[mi][ni][1] + b1v + t0 * w1v;
            Os[(m0 + 8) * 65 + 1 + n0]     = acc[mi][ni][2] + b0v + t8 * w0v;
            Os[(m0 + 8) * 65 + 2 + n0]     = acc[mi][ni][3] + b1v + t8 * w1v;
        }
    }
    __syncthreads();

    if (tid < 128) {
        float s = 0.f;
        #pragma unroll 8
        for (int c = 1; c <= 64; ++c) {
            const float v = Os[tid * 65 + c];
            s += v * v;
        }
        Os[tid * 65] = sqrtf(s + 1.f);
    }
    __syncthreads();

    float4* og = (float4*)(out + (size_t)blk * 128 * 65);
    const float4* ov = (const float4*)Os;
    #pragma unroll 2
    for (int i = tid; i < 128 * 65 / 4; i += 256) og[i] = ov[i];
}

// ---------------- launch ----------------

extern "C" void kernel_launch(void* const* d_in, const int* in_sizes, int n_in,
                              void* d_out, int out_size) {
    const float* x    = (const float*)d_in[0];
    const float* w    = (const float*)d_in[1];
    const float* bias = (const float*)d_in[2];
    float* out = (float*)d_out;

    cudaFuncSetAttribute(lmma_kernel, cudaFuncAttributeMaxDynamicSharedMemorySize, SMEM_TOTAL);

    prep_b_kernel<<<(9 * 64 * 64 + 255) / 256, 256>>>(w);
    lmma_kernel<<<1024, 256, SMEM_TOTAL>>>(x, w, bias, out);
}

// round 4
// speedup vs baseline: 4.6499x; 1.0695x over previous
#include <cuda_runtime.h>
#include <cuda_bf16.h>
#include <cstdint>

// LorentzConv2d: B=32,H=W=64,C=64,OC=64(+time), 3x3 s1 p1.
// Warp mma.sync bf16 hi/lo split (3 MMAs per k16). B pre-baked into
// mma fragment layout in gmem (LDG.128, L1/L2-resident) -> no B smem,
// no B ldmatrix, barrier-free mainloop.

// B fragments: [tap][k16][n8][lane] = {bh0, bh1, bl0, bl1}
__device__ uint4 g_Bf[9 * 4 * 8 * 32];

__device__ __forceinline__ uint32_t pack_bf2(float a, float b) {
    __nv_bfloat162 h = __floats2bfloat162_rn(a, b);
    return *(uint32_t*)&h;
}

__global__ void prep_bfrag_kernel(const float* __restrict__ w) {
    int i = blockIdx.x * blockDim.x + threadIdx.x;
    if (i >= 9 * 4 * 8 * 32) return;
    const int lane = i & 31;
    const int nc   = (i >> 5) & 7;
    const int kc   = (i >> 8) & 3;
    const int tap  = i >> 10;
    const int n  = nc * 8 + (lane >> 2);
    const int k0 = kc * 16 + (lane & 3) * 2;
    // B[n][k]: k = channel c; c==0 excluded (hyperbolic), else w[n*568 + tap*63 + c]
    float v0 = (k0     == 0) ? 0.f : w[n * 568 + tap * 63 + k0];
    float v1 =                        w[n * 568 + tap * 63 + k0 + 1];
    float v2 =                        w[n * 568 + tap * 63 + k0 + 8];
    float v3 =                        w[n * 568 + tap * 63 + k0 + 9];
    uint4 r;
    r.x = pack_bf2(v0, v1);
    r.y = pack_bf2(v2, v3);
    __nv_bfloat162 h0 = *(__nv_bfloat162*)&r.x;
    __nv_bfloat162 h1 = *(__nv_bfloat162*)&r.y;
    r.z = pack_bf2(v0 - __bfloat162float(h0.x), v1 - __bfloat162float(h0.y));
    r.w = pack_bf2(v2 - __bfloat162float(h1.x), v3 - __bfloat162float(h1.y));
    g_Bf[i] = r;
}

// ---------------- helpers ----------------

#define SWZ(o) ((o) ^ (((o) >> 3) & 0x70))

__device__ __forceinline__ uint32_t s2u(const void* p) {
    uint32_t a;
    asm("{ .reg .u64 t; cvta.to.shared.u64 t, %1; cvt.u32.u64 %0, t; }" : "=r"(a) : "l"(p));
    return a;
}

#define LDSM4(r, addr) \
    asm volatile("ldmatrix.sync.aligned.m8n8.x4.shared.b16 {%0,%1,%2,%3}, [%4];" \
        : "=r"((r)[0]), "=r"((r)[1]), "=r"((r)[2]), "=r"((r)[3]) : "r"(addr))

#define MMA(d, a, b0_, b1_) \
    asm volatile("mma.sync.aligned.m16n8k16.row.col.f32.bf16.bf16.f32 " \
        "{%0,%1,%2,%3}, {%4,%5,%6,%7}, {%8,%9}, {%0,%1,%2,%3};" \
        : "+f"((d)[0]), "+f"((d)[1]), "+f"((d)[2]), "+f"((d)[3]) \
        : "r"((a)[0]), "r"((a)[1]), "r"((a)[2]), "r"((a)[3]), "r"(b0_), "r"(b1_))

// ---------------- smem layout (bytes) ----------------
// [0..512)       t (128 f)
// [512..768)     bias (64 f)
// [768..1024)    w0 (64 f)
// [1024..34816)  A_hi : 264 slots (4 rows x 66 halo cols) x 128B, SW128
// [34816..68608) A_lo
// Os (128x65 f = 33280B) overlays A_hi after mainloop.
#define T_OFF    0u
#define BIAS_OFF 512u
#define W0_OFF   768u
#define AHI_OFF  1024u
#define ALO_OFF  34816u
#define SMEM_TOTAL 68608

__global__ __launch_bounds__(256, 2)
void lmma_kernel(const float* __restrict__ x, const float* __restrict__ w,
                 const float* __restrict__ bias, float* __restrict__ out)
{
    extern __shared__ char sm[];
    const uint32_t smb = s2u(sm);
    const int tid  = threadIdx.x;
    const int lane = tid & 31;
    const int wid  = tid >> 5;
    const int wm   = wid & 3;          // m span: 32 rows
    const int wn   = wid >> 2;         // n span: 32 cols
    const int blk  = blockIdx.x;       // 0..1023
    const int b    = blk >> 5;
    const int h0   = (blk & 31) * 2;   // 2 image rows per CTA

    // ---- epilogue params + t ----
    if (tid < 64) {
        ((float*)(sm + BIAS_OFF))[tid] = bias[tid];
        ((float*)(sm + W0_OFF))[tid]   = w[tid * 568];   // W[:,0]
    }
    if (tid < 128) {
        const int ir = tid >> 6, wp = tid & 63;
        float s = 0.f;
        #pragma unroll
        for (int r = 0; r < 3; ++r)
            #pragma unroll
            for (int d = 0; d < 3; ++d) {
                const int hg = h0 + ir + r - 1, wg = wp + d - 1;
                float v = 0.f;
                if ((unsigned)hg < 64u && (unsigned)wg < 64u)
                    v = x[(size_t)(((b * 64 + hg) * 64 + wg)) * 64];   // channel 0
                const float m = fmaxf(v, 1.f);
                s += m * m;
            }
        ((float*)(sm + T_OFF))[tid] = sqrtf(s - 8.f);
    }

    // ---- A load: fp32 -> bf16 hi/lo into swizzled smem (once) ----
    {
        const int c4 = tid & 15;
        for (int slot = tid >> 4; slot < 264; slot += 16) {
            const int r = slot / 66, c = slot - r * 66;
            const int hg = h0 - 1 + r, wg = c - 1;
            const uint32_t o = SWZ((uint32_t)slot * 128u + (uint32_t)c4 * 8u);
            float4 v = make_float4(0.f, 0.f, 0.f, 0.f);
            if ((unsigned)hg < 64u && (unsigned)wg < 64u)
                v = *(const float4*)(x + (size_t)(((b * 64 + hg) * 64 + wg)) * 64 + c4 * 4);
            uint2 hi, lo;
            hi.x = pack_bf2(v.x, v.y);
            hi.y = pack_bf2(v.z, v.w);
            __nv_bfloat162 h0v = *(__nv_bfloat162*)&hi.x;
            __nv_bfloat162 h1v = *(__nv_bfloat162*)&hi.y;
            lo.x = pack_bf2(v.x - __bfloat162float(h0v.x), v.y - __bfloat162float(h0v.y));
            lo.y = pack_bf2(v.z - __bfloat162float(h1v.x), v.w - __bfloat162float(h1v.y));
            *(uint2*)(sm + AHI_OFF + o) = hi;
            *(uint2*)(sm + ALO_OFF + o) = lo;
        }
    }
    __syncthreads();

    // ---- per-lane invariants ----
    const uint32_t ahalf = (uint32_t)(lane >> 4);
    const int mloc[2] = { wm * 32 + (lane & 15), wm * 32 + 16 + (lane & 15) };
    const uint4* bptr = g_Bf + (size_t)(wn * 4) * 32 + lane;   // + ((tap*4+k)*8 + j)*32

    float acc[2][4][4];
    #pragma unroll
    for (int mi = 0; mi < 2; ++mi)
        #pragma unroll
        for (int ni = 0; ni < 4; ++ni)
            #pragma unroll
            for (int j = 0; j < 4; ++j) acc[mi][ni][j] = 0.f;

    // ---- barrier-free mainloop: 9 taps x 4 k16 steps ----
    uint4 bb[2][4];
    #pragma unroll
    for (int j = 0; j < 4; ++j) bb[0][j] = bptr[j * 32];

    for (int tap = 0; tap < 9; ++tap) {
        const int r = tap / 3, dw = tap - r * 3;
        uint32_t abase[2], asx[2];
        #pragma unroll
        for (int mi = 0; mi < 2; ++mi) {
            const int ir = mloc[mi] >> 6, wp = mloc[mi] & 63;
            const int P = (ir + r) * 66 + wp + dw;
            abase[mi] = (uint32_t)P * 128u;
            asx[mi]   = (uint32_t)(P & 7);
        }

        #pragma unroll
        for (int k = 0; k < 4; ++k) {
            const int cur = k & 1, nxt = cur ^ 1;
            // prefetch next B frags (1 step ahead)
            if (!(tap == 8 && k == 3)) {
                const int ntap = (k == 3) ? tap + 1 : tap;
                const int nk   = (k + 1) & 3;
                const uint4* p = bptr + (size_t)((ntap * 4 + nk) * 8) * 32;
                #pragma unroll
                for (int j = 0; j < 4; ++j) bb[nxt][j] = p[j * 32];
            }
            // A frags via ldmatrix
            uint32_t ah[2][4], al[2][4];
            #pragma unroll
            for (int mi = 0; mi < 2; ++mi) {
                const uint32_t ao = abase[mi] +
                    ((((uint32_t)(k * 2) + ahalf) ^ asx[mi]) << 4);
                LDSM4(ah[mi], smb + AHI_OFF + ao);
                LDSM4(al[mi], smb + ALO_OFF + ao);
            }
            // 12 MMAs: hi*hi + hi*lo + lo*hi
            #pragma unroll
            for (int mi = 0; mi < 2; ++mi)
                #pragma unroll
                for (int j = 0; j < 4; ++j) {
                    MMA(acc[mi][j], ah[mi], bb[cur][j].x, bb[cur][j].y);
                    MMA(acc[mi][j], ah[mi], bb[cur][j].z, bb[cur][j].w);
                    MMA(acc[mi][j], al[mi], bb[cur][j].x, bb[cur][j].y);
                }
        }
    }

    // ---- epilogue: fuse bias + t*W[:,0], |y|^2, y_time, writeback ----
    __syncthreads();   // all LDSM done before Os overlays A_hi

    const float* ts  = (const float*)(sm + T_OFF);
    const float* bs  = (const float*)(sm + BIAS_OFF);
    const float* w0s = (const float*)(sm + W0_OFF);
    float* Os = (float*)(sm + AHI_OFF);

    #pragma unroll
    for (int mi = 0; mi < 2; ++mi) {
        const int m0 = wm * 32 + mi * 16 + (lane >> 2);
        const float t0 = ts[m0], t8 = ts[m0 + 8];
        #pragma unroll
        for (int ni = 0; ni < 4; ++ni) {
            const int n0 = wn * 32 + ni * 8 + (lane & 3) * 2;
            const float b0v = bs[n0],  b1v = bs[n0 + 1];
            const float w0v = w0s[n0], w1v = w0s[n0 + 1];
            Os[m0 * 65 + 1 + n0]       = acc[mi][ni][0] + b0v + t0 * w0v;
            Os[m0 * 65 + 2 + n0]       = acc[mi][ni][1] + b1v + t0 * w1v;
            Os[(m0 + 8) * 65 + 1 + n0] = acc[mi][ni][2] + b0v + t8 * w0v;
            Os[(m0 + 8) * 65 + 2 + n0] = acc[mi][ni][3] + b1v + t8 * w1v;
        }
    }
    __syncthreads();

    if (tid < 128) {
        float s = 0.f;
        #pragma unroll 8
        for (int c = 1; c <= 64; ++c) {
            const float v = Os[tid * 65 + c];
            s += v * v;
        }
        Os[tid * 65] = sqrtf(s + 1.f);
    }
    __syncthreads();

    float4* og = (float4*)(out + (size_t)blk * 128 * 65);
    const float4* ov = (const float4*)Os;
    #pragma unroll 2
    for (int i = tid; i < 128 * 65 / 4; i += 256) og[i] = ov[i];
}

// ---------------- launch ----------------

extern "C" void kernel_launch(void* const* d_in, const int* in_sizes, int n_in,
                              void* d_out, int out_size) {
    const float* x    = (const float*)d_in[0];
    const float* w    = (const float*)d_in[1];
    const float* bias = (const float*)d_in[2];
    float* out = (float*)d_out;

    cudaFuncSetAttribute(lmma_kernel, cudaFuncAttributeMaxDynamicSharedMemorySize, SMEM_TOTAL);

    prep_bfrag_kernel<<<(9 * 4 * 8 * 32 + 255) / 256, 256>>>(w);
    lmma_kernel<<<1024, 256, SMEM_TOTAL>>>(x, w, bias, out);
}

// round 5
// speedup vs baseline: 7.5519x; 1.6241x over previous
#include <cuda_runtime.h>
#include <cuda_fp16.h>
#include <cstdint>

// LorentzConv2d: B=32,H=W=64,C=64,OC=64(+time), 3x3 s1 p1.
// Warp mma.sync fp16 single-pass (fp32 accum). Error model ~4e-4 < 1e-3 gate.
// B pre-baked into mma fragment layout in gmem (LDG.128, L2-resident).

// B fragments: [tap][k16][npair][lane] = {j0.b0, j0.b1, j1.b0, j1.b1}
// npair covers n = pair*16 + j*8 + lane/4  (j = 0,1)
__device__ uint4 g_Bf[9 * 4 * 4 * 32];

__device__ __forceinline__ uint32_t pack_h2(float a, float b) {
    __half2 h = __floats2half2_rn(a, b);
    return *(uint32_t*)&h;
}

__global__ void prep_bfrag_kernel(const float* __restrict__ w) {
    int i = blockIdx.x * blockDim.x + threadIdx.x;
    if (i >= 9 * 4 * 4 * 32) return;
    const int lane = i & 31;
    const int pair = (i >> 5) & 3;
    const int kc   = (i >> 7) & 3;
    const int tap  = i >> 9;
    const int k0 = kc * 16 + (lane & 3) * 2;
    uint4 r;
    #pragma unroll
    for (int j = 0; j < 2; ++j) {
        const int n = pair * 16 + j * 8 + (lane >> 2);
        // B[n][c]: c==0 excluded (hyperbolic), else w[n*568 + tap*63 + c]
        float v0 = (k0 == 0) ? 0.f : w[n * 568 + tap * 63 + k0];
        float v1 = w[n * 568 + tap * 63 + k0 + 1];
        float v2 = w[n * 568 + tap * 63 + k0 + 8];
        float v3 = w[n * 568 + tap * 63 + k0 + 9];
        if (j == 0) { r.x = pack_h2(v0, v1); r.y = pack_h2(v2, v3); }
        else        { r.z = pack_h2(v0, v1); r.w = pack_h2(v2, v3); }
    }
    g_Bf[i] = r;
}

// ---------------- helpers ----------------

#define SWZ(o) ((o) ^ (((o) >> 3) & 0x70))

__device__ __forceinline__ uint32_t s2u(const void* p) {
    uint32_t a;
    asm("{ .reg .u64 t; cvta.to.shared.u64 t, %1; cvt.u32.u64 %0, t; }" : "=r"(a) : "l"(p));
    return a;
}

#define LDSM4(r, addr) \
    asm volatile("ldmatrix.sync.aligned.m8n8.x4.shared.b16 {%0,%1,%2,%3}, [%4];" \
        : "=r"((r)[0]), "=r"((r)[1]), "=r"((r)[2]), "=r"((r)[3]) : "r"(addr))

#define MMA(d, a, b0_, b1_) \
    asm volatile("mma.sync.aligned.m16n8k16.row.col.f32.f16.f16.f32 " \
        "{%0,%1,%2,%3}, {%4,%5,%6,%7}, {%8,%9}, {%0,%1,%2,%3};" \
        : "+f"((d)[0]), "+f"((d)[1]), "+f"((d)[2]), "+f"((d)[3]) \
        : "r"((a)[0]), "r"((a)[1]), "r"((a)[2]), "r"((a)[3]), "r"(b0_), "r"(b1_))

// ---------------- smem layout (bytes) ----------------
// [0..512)      t (128 f)
// [512..768)    bias (64 f)
// [768..1024)   w0 (64 f)
// [1024..34816) A : 264 slots (4 rows x 66 halo cols) x 128B (64ch fp16), SW128
// Os (128x65 f = 33280B) overlays A after mainloop.
#define T_OFF    0u
#define BIAS_OFF 512u
#define W0_OFF   768u
#define A_OFF    1024u
#define SMEM_TOTAL 34816

__global__ __launch_bounds__(256, 3)
void lmma_kernel(const float* __restrict__ x, const float* __restrict__ w,
                 const float* __restrict__ bias, float* __restrict__ out)
{
    extern __shared__ char sm[];
    const uint32_t smb = s2u(sm);
    const int tid  = threadIdx.x;
    const int lane = tid & 31;
    const int wid  = tid >> 5;
    const int wm   = wid & 3;          // m span: 32 rows
    const int wn   = wid >> 2;         // n span: 32 cols
    const int blk  = blockIdx.x;       // 0..1023
    const int b    = blk >> 5;
    const int h0   = (blk & 31) * 2;   // 2 image rows per CTA

    // ---- epilogue params + t ----
    if (tid < 64) {
        ((float*)(sm + BIAS_OFF))[tid] = bias[tid];
        ((float*)(sm + W0_OFF))[tid]   = w[tid * 568];   // W[:,0]
    }
    if (tid < 128) {
        const int ir = tid >> 6, wp = tid & 63;
        float s = 0.f;
        #pragma unroll
        for (int r = 0; r < 3; ++r)
            #pragma unroll
            for (int d = 0; d < 3; ++d) {
                const int hg = h0 + ir + r - 1, wg = wp + d - 1;
                float v = 0.f;
                if ((unsigned)hg < 64u && (unsigned)wg < 64u)
                    v = x[(size_t)(((b * 64 + hg) * 64 + wg)) * 64];   // channel 0
                const float m = fmaxf(v, 1.f);
                s += m * m;
            }
        ((float*)(sm + T_OFF))[tid] = sqrtf(s - 8.f);
    }

    // ---- A load: fp32 -> fp16 into swizzled smem (once) ----
    {
        const int c4 = tid & 15;
        for (int slot = tid >> 4; slot < 264; slot += 16) {
            const int r = slot / 66, c = slot - r * 66;
            const int hg = h0 - 1 + r, wg = c - 1;
            const uint32_t o = SWZ((uint32_t)slot * 128u + (uint32_t)c4 * 8u);
            float4 v = make_float4(0.f, 0.f, 0.f, 0.f);
            if ((unsigned)hg < 64u && (unsigned)wg < 64u)
                v = *(const float4*)(x + (size_t)(((b * 64 + hg) * 64 + wg)) * 64 + c4 * 4);
            uint2 hv;
            hv.x = pack_h2(v.x, v.y);
            hv.y = pack_h2(v.z, v.w);
            *(uint2*)(sm + A_OFF + o) = hv;
        }
    }
    __syncthreads();

    // ---- per-lane invariants ----
    const uint32_t ahalf = (uint32_t)(lane >> 4);
    const int mloc[2] = { wm * 32 + (lane & 15), wm * 32 + 16 + (lane & 15) };
    // warp wn uses npairs wn*2, wn*2+1
    const uint4* bptr = g_Bf + (size_t)(wn * 2) * 32 + lane;  // + (kstep*4 + pp)*32

    float acc[2][4][4];
    #pragma unroll
    for (int mi = 0; mi < 2; ++mi)
        #pragma unroll
        for (int ni = 0; ni < 4; ++ni)
            #pragma unroll
            for (int j = 0; j < 4; ++j) acc[mi][ni][j] = 0.f;

    // ---- barrier-free mainloop: 9 taps x 4 k16 steps, B double-buffered ----
    uint4 bb[2][2];
    bb[0][0] = bptr[0];
    bb[0][1] = bptr[32];

    for (int tap = 0; tap < 9; ++tap) {
        const int r = tap / 3, dw = tap - r * 3;
        uint32_t abase[2], asx[2];
        #pragma unroll
        for (int mi = 0; mi < 2; ++mi) {
            const int ir = mloc[mi] >> 6, wp = mloc[mi] & 63;
            const int P = (ir + r) * 66 + wp + dw;
            abase[mi] = (uint32_t)P * 128u;
            asx[mi]   = (uint32_t)(P & 7);
        }

        #pragma unroll
        for (int k = 0; k < 4; ++k) {
            const int cur = k & 1, nxt = cur ^ 1;
            if (!(tap == 8 && k == 3)) {
                const int nstep = ((k == 3) ? (tap + 1) * 4 : tap * 4 + k + 1);
                const uint4* p = bptr + (size_t)(nstep * 4) * 32;
                bb[nxt][0] = p[0];
                bb[nxt][1] = p[32];
            }
            uint32_t ah[2][4];
            #pragma unroll
            for (int mi = 0; mi < 2; ++mi) {
                const uint32_t ao = abase[mi] +
                    ((((uint32_t)(k * 2) + ahalf) ^ asx[mi]) << 4);
                LDSM4(ah[mi], smb + A_OFF + ao);
            }
            #pragma unroll
            for (int mi = 0; mi < 2; ++mi) {
                MMA(acc[mi][0], ah[mi], bb[cur][0].x, bb[cur][0].y);
                MMA(acc[mi][1], ah[mi], bb[cur][0].z, bb[cur][0].w);
                MMA(acc[mi][2], ah[mi], bb[cur][1].x, bb[cur][1].y);
                MMA(acc[mi][3], ah[mi], bb[cur][1].z, bb[cur][1].w);
            }
        }
    }

    // ---- epilogue: fuse bias + t*W[:,0], |y|^2, y_time, writeback ----
    __syncthreads();   // all LDSM done before Os overlays A

    const float* ts  = (const float*)(sm + T_OFF);
    const float* bs  = (const float*)(sm + BIAS_OFF);
    const float* w0s = (const float*)(sm + W0_OFF);
    float* Os = (float*)(sm + A_OFF);

    #pragma unroll
    for (int mi = 0; mi < 2; ++mi) {
        const int m0 = wm * 32 + mi * 16 + (lane >> 2);
        const float t0 = ts[m0], t8 = ts[m0 + 8];
        #pragma unroll
        for (int ni = 0; ni < 4; ++ni) {
            const int n0 = wn * 32 + ni * 8 + (lane & 3) * 2;
            const float b0v = bs[n0],  b1v = bs[n0 + 1];
            const float w0v = w0s[n0], w1v = w0s[n0 + 1];
            Os[m0 * 65 + 1 + n0]       = acc[mi][ni][0] + b0v + t0 * w0v;
            Os[m0 * 65 + 2 + n0]       = acc[mi][ni][1] + b1v + t0 * w1v;
            Os[(m0 + 8) * 65 + 1 + n0] = acc[mi][ni][2] + b0v + t8 * w0v;
            Os[(m0 + 8) * 65 + 2 + n0] = acc[mi][ni][3] + b1v + t8 * w1v;
        }
    }
    __syncthreads();

    if (tid < 128) {
        float s = 0.f;
        #pragma unroll 8
        for (int c = 1; c <= 64; ++c) {
            const float v = Os[tid * 65 + c];
            s += v * v;
        }
        Os[tid * 65] = sqrtf(s + 1.f);
    }
    __syncthreads();

    float4* og = (float4*)(out + (size_t)blk * 128 * 65);
    const float4* ov = (const float4*)Os;
    #pragma unroll 2
    for (int i = tid; i < 128 * 65 / 4; i += 256) og[i] = ov[i];
}

// ---------------- launch ----------------

extern "C" void kernel_launch(void* const* d_in, const int* in_sizes, int n_in,
                              void* d_out, int out_size) {
    const float* x    = (const float*)d_in[0];
    const float* w    = (const float*)d_in[1];
    const float* bias = (const float*)d_in[2];
    float* out = (float*)d_out;

    cudaFuncSetAttribute(lmma_kernel, cudaFuncAttributeMaxDynamicSharedMemorySize, SMEM_TOTAL);

    prep_bfrag_kernel<<<(9 * 4 * 4 * 32 + 255) / 256, 256>>>(w);
    lmma_kernel<<<1024, 256, SMEM_TOTAL>>>(x, w, bias, out);
}